// round 4
// baseline (speedup 1.0000x reference)
#include <cuda_runtime.h>

#define BATCH 16
#define CHAN  3
#define HH 512
#define WW 512
#define TILE_ROWS 16
#define HALO 6
#define MAX_SROWS (TILE_ROWS + 2 * HALO)   // 28
#define NTHREADS 512
#define SMEM_BYTES (CHAN * MAX_SROWS * WW * 4)   // 172032 bytes
#define DELTA2 1e-6f
#define ALPHA  0.45f

__global__ void zero_out_kernel(float* out, int n) {
    int i = blockIdx.x * blockDim.x + threadIdx.x;
    if (i < n) out[i] = 0.0f;
}

extern __shared__ float s_tile[];   // [CHAN][MAX_SROWS][WW]

__global__ __launch_bounds__(NTHREADS, 1)
void photometric_tile_kernel(const float* __restrict__ frame1,
                             const float* __restrict__ frame2,
                             const float* __restrict__ flow,
                             float* __restrict__ out) {
    const int HW = HH * WW;
    const int tile = blockIdx.x;          // 0..31
    const int b    = blockIdx.y;          // 0..15
    const int ty0  = tile * TILE_ROWS;
    const int t_lo = max(0, ty0 - HALO);
    const int t_hi = min(HH - 1, ty0 + TILE_ROWS - 1 + HALO);
    const int nrows = t_hi - t_lo + 1;
    const int tid = threadIdx.x;

    const float* f2b = frame2 + (size_t)b * CHAN * HW;

    // ---- stage frame2 rows [t_lo, t_hi] for all channels (float4 coalesced) ----
    #pragma unroll
    for (int c = 0; c < CHAN; c++) {
        const float4* src = (const float4*)(f2b + (size_t)c * HW + (size_t)t_lo * WW);
        float4* dst = (float4*)(s_tile + c * MAX_SROWS * WW);
        const int n4 = nrows * (WW / 4);
        for (int i = tid; i < n4; i += NTHREADS) dst[i] = src[i];
    }
    __syncthreads();

    const int x = tid;                    // 0..511, full row per block
    const float scale = (float)(WW - 1) / (float)WW;   // W==H so shared
    const float* f1b  = frame1 + (size_t)b * CHAN * HW;
    const float* flx  = flow + (size_t)(b * 2 + 0) * HW;
    const float* fly  = flow + (size_t)(b * 2 + 1) * HW;

    float acc = 0.0f;

    #pragma unroll 4
    for (int r = 0; r < TILE_ROWS; r++) {
        const int y  = ty0 + r;
        const int hw = y * WW + x;

        const float fx = __ldg(flx + hw);
        const float fy = __ldg(fly + hw);

        float ix = ((float)x + fx) * scale;
        float iy = ((float)y + fy) * scale;
        ix = fminf(fmaxf(ix, 0.0f), (float)(WW - 1));
        iy = fminf(fmaxf(iy, 0.0f), (float)(HH - 1));

        const float x0f = floorf(ix);
        const float y0f = floorf(iy);
        const float wx = ix - x0f;
        const float wy = iy - y0f;
        const int x0 = (int)x0f;
        const int y0 = (int)y0f;
        const int x1 = min(x0 + 1, WW - 1);
        const int y1 = min(y0 + 1, HH - 1);

        const float* f1p = f1b + hw;

        if (y0 >= t_lo && y1 <= t_hi) {
            // fast path: gather from shared tile
            const int r0 = (y0 - t_lo) * WW;
            const int r1 = (y1 - t_lo) * WW;
            #pragma unroll
            for (int c = 0; c < CHAN; c++) {
                const float* t = s_tile + c * MAX_SROWS * WW;
                const float v00 = t[r0 + x0];
                const float v01 = t[r0 + x1];
                const float v10 = t[r1 + x0];
                const float v11 = t[r1 + x1];
                const float top = fmaf(v01 - v00, wx, v00);
                const float bot = fmaf(v11 - v10, wx, v10);
                const float wv  = fmaf(bot - top, wy, top);
                const float d = __ldg(f1p + c * HW) - wv;
                acc += __powf(fmaf(d, d, DELTA2), ALPHA);
            }
        } else {
            // rare fallback: exact global gathers
            const int i00 = y0 * WW + x0;
            const int i01 = y0 * WW + x1;
            const int i10 = y1 * WW + x0;
            const int i11 = y1 * WW + x1;
            #pragma unroll
            for (int c = 0; c < CHAN; c++) {
                const float* p = f2b + (size_t)c * HW;
                const float v00 = __ldg(p + i00);
                const float v01 = __ldg(p + i01);
                const float v10 = __ldg(p + i10);
                const float v11 = __ldg(p + i11);
                const float top = fmaf(v01 - v00, wx, v00);
                const float bot = fmaf(v11 - v10, wx, v10);
                const float wv  = fmaf(bot - top, wy, top);
                const float d = __ldg(f1p + c * HW) - wv;
                acc += __powf(fmaf(d, d, DELTA2), ALPHA);
            }
        }
    }

    // ---- block reduction ----
    #pragma unroll
    for (int off = 16; off > 0; off >>= 1)
        acc += __shfl_down_sync(0xFFFFFFFFu, acc, off);

    __shared__ float warp_sums[NTHREADS / 32];
    const int lane = tid & 31;
    const int wid  = tid >> 5;
    if (lane == 0) warp_sums[wid] = acc;
    __syncthreads();

    if (wid == 0) {
        float s = (lane < (NTHREADS / 32)) ? warp_sums[lane] : 0.0f;
        #pragma unroll
        for (int off = 8; off > 0; off >>= 1)
            s += __shfl_down_sync(0xFFFFFFFFu, s, off);
        if (lane == 0) atomicAdd(out, s);
    }
}

extern "C" void kernel_launch(void* const* d_in, const int* in_sizes, int n_in,
                              void* d_out, int out_size) {
    const float* frame1 = (const float*)d_in[0];
    const float* frame2 = (const float*)d_in[1];
    const float* flow   = (const float*)d_in[2];
    float* out = (float*)d_out;

    // Host-side attribute set: non-stream API, capture-safe, idempotent,
    // called unconditionally on every invocation (deterministic).
    cudaFuncSetAttribute(photometric_tile_kernel,
                         cudaFuncAttributeMaxDynamicSharedMemorySize, SMEM_BYTES);

    zero_out_kernel<<<(out_size + 255) / 256, 256>>>(out, out_size);

    dim3 grid(HH / TILE_ROWS, BATCH);   // 32 x 16
    photometric_tile_kernel<<<grid, NTHREADS, SMEM_BYTES>>>(frame1, frame2, flow, out);
}

// round 5
// speedup vs baseline: 1.6188x; 1.6188x over previous
#include <cuda_runtime.h>

#define BATCH 16
#define CHAN  3
#define HH 512
#define WW 512
#define TILE_ROWS 8
#define HALO 5
#define SROWS (TILE_ROWS + 2 * HALO)       // 18
#define NTHREADS 512
#define SMEM_FLOATS (CHAN * SROWS * WW)    // 27648
#define SMEM_BYTES (SMEM_FLOATS * 4)       // 110592 (108KB) -> 2 blocks/SM
#define DELTA2 1e-6f
#define ALPHA  0.45f

__global__ void zero_out_kernel(float* out, int n) {
    int i = blockIdx.x * blockDim.x + threadIdx.x;
    if (i < n) out[i] = 0.0f;
}

extern __shared__ float s_tile[];          // [CHAN][SROWS][WW]

__global__ __launch_bounds__(NTHREADS, 2)
void photometric_tile_kernel(const float* __restrict__ frame1,
                             const float* __restrict__ frame2,
                             const float* __restrict__ flow,
                             float* __restrict__ out) {
    const int HW = HH * WW;
    const int tile = blockIdx.x;           // 0..63
    const int b    = blockIdx.y;           // 0..15
    const int ty0  = tile * TILE_ROWS;
    const int t_lo = max(0, ty0 - HALO);
    const int t_hi = min(HH - 1, ty0 + TILE_ROWS - 1 + HALO);
    const int nrows = t_hi - t_lo + 1;     // <= 18
    const int tid = threadIdx.x;

    const float* f2b = frame2 + (size_t)b * CHAN * HW;

    // ---- stage frame2 rows [t_lo, t_hi], all channels, float4 coalesced ----
    #pragma unroll
    for (int c = 0; c < CHAN; c++) {
        const float4* src = (const float4*)(f2b + (size_t)c * HW + (size_t)t_lo * WW);
        float4* dst = (float4*)(s_tile + c * SROWS * WW);
        const int n4 = nrows * (WW / 4);
        for (int i = tid; i < n4; i += NTHREADS) dst[i] = src[i];
    }
    __syncthreads();

    const int x = tid;                     // full row per block
    const float scale = (float)(WW - 1) / (float)WW;
    const float* f1b = frame1 + (size_t)b * CHAN * HW;
    const float* flx = flow + (size_t)(b * 2 + 0) * HW;
    const float* fly = flow + (size_t)(b * 2 + 1) * HW;

    float acc = 0.0f;

    #pragma unroll 2
    for (int r = 0; r < TILE_ROWS; r++) {
        const int y  = ty0 + r;
        const int hw = y * WW + x;

        const float fx = __ldg(flx + hw);
        const float fy = __ldg(fly + hw);

        float ix = ((float)x + fx) * scale;
        float iy = ((float)y + fy) * scale;
        ix = fminf(fmaxf(ix, 0.0f), (float)(WW - 1));
        iy = fminf(fmaxf(iy, 0.0f), (float)(HH - 1));

        const float x0f = floorf(ix);
        const float y0f = floorf(iy);
        const float wx = ix - x0f;
        const float wy = iy - y0f;
        const int x0 = (int)x0f;
        const int y0 = (int)y0f;
        const int x1 = min(x0 + 1, WW - 1);
        const int y1 = min(y0 + 1, HH - 1);

        const float* f1p = f1b + hw;

        if (y0 >= t_lo && y1 <= t_hi) {
            const int r0 = (y0 - t_lo) * WW;
            const int r1 = (y1 - t_lo) * WW;
            #pragma unroll
            for (int c = 0; c < CHAN; c++) {
                const float* t = s_tile + c * SROWS * WW;
                const float v00 = t[r0 + x0];
                const float v01 = t[r0 + x1];
                const float v10 = t[r1 + x0];
                const float v11 = t[r1 + x1];
                const float top = fmaf(v01 - v00, wx, v00);
                const float bot = fmaf(v11 - v10, wx, v10);
                const float wv  = fmaf(bot - top, wy, top);
                const float d = __ldg(f1p + c * HW) - wv;
                acc += __powf(fmaf(d, d, DELTA2), ALPHA);
            }
        } else {
            // ~5 pixels in the whole problem: exact global gathers
            const int i00 = y0 * WW + x0;
            const int i01 = y0 * WW + x1;
            const int i10 = y1 * WW + x0;
            const int i11 = y1 * WW + x1;
            #pragma unroll
            for (int c = 0; c < CHAN; c++) {
                const float* p = f2b + (size_t)c * HW;
                const float v00 = __ldg(p + i00);
                const float v01 = __ldg(p + i01);
                const float v10 = __ldg(p + i10);
                const float v11 = __ldg(p + i11);
                const float top = fmaf(v01 - v00, wx, v00);
                const float bot = fmaf(v11 - v10, wx, v10);
                const float wv  = fmaf(bot - top, wy, top);
                const float d = __ldg(f1p + c * HW) - wv;
                acc += __powf(fmaf(d, d, DELTA2), ALPHA);
            }
        }
    }

    // ---- block reduction ----
    #pragma unroll
    for (int off = 16; off > 0; off >>= 1)
        acc += __shfl_down_sync(0xFFFFFFFFu, acc, off);

    __shared__ float warp_sums[NTHREADS / 32];
    const int lane = tid & 31;
    const int wid  = tid >> 5;
    if (lane == 0) warp_sums[wid] = acc;
    __syncthreads();

    if (wid == 0) {
        float s = (lane < (NTHREADS / 32)) ? warp_sums[lane] : 0.0f;
        #pragma unroll
        for (int off = 8; off > 0; off >>= 1)
            s += __shfl_down_sync(0xFFFFFFFFu, s, off);
        if (lane == 0) atomicAdd(out, s);
    }
}

extern "C" void kernel_launch(void* const* d_in, const int* in_sizes, int n_in,
                              void* d_out, int out_size) {
    const float* frame1 = (const float*)d_in[0];
    const float* frame2 = (const float*)d_in[1];
    const float* flow   = (const float*)d_in[2];
    float* out = (float*)d_out;

    // Host-side attribute set: capture-safe, idempotent, unconditional.
    cudaFuncSetAttribute(photometric_tile_kernel,
                         cudaFuncAttributeMaxDynamicSharedMemorySize, SMEM_BYTES);

    zero_out_kernel<<<(out_size + 255) / 256, 256>>>(out, out_size);

    dim3 grid(HH / TILE_ROWS, BATCH);      // 64 x 16 = 1024 blocks
    photometric_tile_kernel<<<grid, NTHREADS, SMEM_BYTES>>>(frame1, frame2, flow, out);
}

// round 6
// speedup vs baseline: 2.6600x; 1.6432x over previous
#include <cuda_runtime.h>

#define BATCH 16
#define CHAN  3
#define HH 512
#define WW 512
#define ROWS_PER_THREAD 4
#define NTHREADS 256
#define DELTA2 1e-6f

__global__ void zero_out_kernel(float* out, int n) {
    int i = blockIdx.x * blockDim.x + threadIdx.x;
    if (i < n) out[i] = 0.0f;
}

// t^0.45 for t in [1e-6, 1.01], FMA/ALU pipes only (no MUFU).
// abs err on log2 ~1.4e-4 -> rel err on result ~5e-5.
__device__ __forceinline__ float pow045(float t) {
    int ti = __float_as_int(t);
    int e = (ti >> 23) - 127;
    float m = __int_as_float((ti & 0x007FFFFF) | 0x3F800000);  // [1,2)
    if (m >= 1.5f) { m *= 0.5f; e += 1; }                       // m in [0.75,1.5)
    float x = m - 1.0f;                                         // [-0.25, 0.5)
    // ln(1+x) via deg-9 alternating series (Horner)
    float p = 0.111111111f;            // 1/9
    p = fmaf(p, x, -0.125f);
    p = fmaf(p, x,  0.142857143f);
    p = fmaf(p, x, -0.166666667f);
    p = fmaf(p, x,  0.2f);
    p = fmaf(p, x, -0.25f);
    p = fmaf(p, x,  0.333333333f);
    p = fmaf(p, x, -0.5f);
    p = fmaf(p, x,  1.0f);
    float lnm = x * p;
    // y = 0.45 * log2(t) = 0.45*e + (0.45/ln2)*ln(m)
    float y = fmaf(0.64921272f, lnm, 0.45f * (float)e);         // in [-9, 0.01]
    float fk = floorf(y);
    float f  = y - fk;                                          // [0,1)
    int   k  = (int)fk;                                         // [-9, 0]
    // 2^f = e^(f*ln2), deg-6 Taylor
    float u = f * 0.69314718f;
    float q = 0.00138888889f;          // 1/720
    q = fmaf(q, u, 0.00833333333f);    // 1/120
    q = fmaf(q, u, 0.0416666667f);     // 1/24
    q = fmaf(q, u, 0.166666667f);      // 1/6
    q = fmaf(q, u, 0.5f);
    q = fmaf(q, u, 1.0f);
    q = fmaf(q, u, 1.0f);
    float scale = __int_as_float((k + 127) << 23);              // exp >= 118, safe
    return q * scale;
}

__global__ __launch_bounds__(NTHREADS)
void photometric_kernel(const float* __restrict__ frame1,
                        const float* __restrict__ frame2,
                        const float* __restrict__ flow,
                        float* __restrict__ out) {
    const int HW = HH * WW;
    // x: 32-consecutive lanes (optimal gather sector packing); 4 rows deep per thread.
    const int x  = blockIdx.x * NTHREADS + threadIdx.x;   // gridDim.x = WW/NTHREADS
    const int y0 = blockIdx.y * ROWS_PER_THREAD;          // gridDim.y = HH/4
    const int b  = blockIdx.z;                            // gridDim.z = BATCH

    const float* f1b = frame1 + (size_t)b * CHAN * HW;
    const float* f2b = frame2 + (size_t)b * CHAN * HW;
    const float* flx = flow + (size_t)(b * 2 + 0) * HW;
    const float* fly = flow + (size_t)(b * 2 + 1) * HW;
    const float scale = (float)(WW - 1) / (float)WW;      // W==H

    float acc = 0.0f;

    #pragma unroll
    for (int r = 0; r < ROWS_PER_THREAD; r++) {
        const int y  = y0 + r;
        const int hw = y * WW + x;

        const float fx = __ldg(flx + hw);
        const float fy = __ldg(fly + hw);

        float ix = ((float)x + fx) * scale;
        float iy = ((float)y + fy) * scale;
        ix = fminf(fmaxf(ix, 0.0f), (float)(WW - 1));
        iy = fminf(fmaxf(iy, 0.0f), (float)(HH - 1));

        const float x0f = floorf(ix);
        const float y0f = floorf(iy);
        const float wx = ix - x0f;
        const float wy = iy - y0f;
        const int x0 = (int)x0f;
        const int yi0 = (int)y0f;
        const int x1 = min(x0 + 1, WW - 1);
        const int yi1 = min(yi0 + 1, HH - 1);

        const int i00 = yi0 * WW + x0;
        const int i01 = yi0 * WW + x1;
        const int i10 = yi1 * WW + x0;
        const int i11 = yi1 * WW + x1;

        #pragma unroll
        for (int c = 0; c < CHAN; c++) {
            const float* p = f2b + (size_t)c * HW;
            const float v00 = __ldg(p + i00);
            const float v01 = __ldg(p + i01);
            const float v10 = __ldg(p + i10);
            const float v11 = __ldg(p + i11);
            const float top = fmaf(v01 - v00, wx, v00);
            const float bot = fmaf(v11 - v10, wx, v10);
            const float wv  = fmaf(bot - top, wy, top);
            const float d = __ldg(f1b + c * HW + hw) - wv;
            acc += pow045(fmaf(d, d, DELTA2));
        }
    }

    // ---- block reduction ----
    #pragma unroll
    for (int off = 16; off > 0; off >>= 1)
        acc += __shfl_down_sync(0xFFFFFFFFu, acc, off);

    __shared__ float warp_sums[NTHREADS / 32];
    const int lane = threadIdx.x & 31;
    const int wid  = threadIdx.x >> 5;
    if (lane == 0) warp_sums[wid] = acc;
    __syncthreads();

    if (wid == 0) {
        float s = (lane < (NTHREADS / 32)) ? warp_sums[lane] : 0.0f;
        #pragma unroll
        for (int off = 4; off > 0; off >>= 1)
            s += __shfl_down_sync(0xFFFFFFFFu, s, off);
        if (lane == 0) atomicAdd(out, s);
    }
}

extern "C" void kernel_launch(void* const* d_in, const int* in_sizes, int n_in,
                              void* d_out, int out_size) {
    const float* frame1 = (const float*)d_in[0];
    const float* frame2 = (const float*)d_in[1];
    const float* flow   = (const float*)d_in[2];
    float* out = (float*)d_out;

    zero_out_kernel<<<(out_size + 255) / 256, 256>>>(out, out_size);

    dim3 grid(WW / NTHREADS, HH / ROWS_PER_THREAD, BATCH);  // 2 x 128 x 16
    photometric_kernel<<<grid, NTHREADS>>>(frame1, frame2, flow, out);
}